// round 8
// baseline (speedup 1.0000x reference)
#include <cuda_runtime.h>
#include <cstdint>

// CIRNet: T=2^20 rows x 18 feats. out = [r_predicts(N), regs(N), dts(N)], N=T-1.
// Persistent kernel, one wave (147 CTAs, 896 thr):
//   Phase A: DIRECT register loading -- each thread owns 8 consecutive rows
//            (576B, 16B-aligned) and reads them as 36 float4 LDGs (9-deep MLP
//            per pair x 28 warps saturates DRAM). dt/p computed straight into
//            scan registers; no smem staging, no tile loop, no mbarriers.
//            regs/dts staged in smem only to coalesce the odd-offset streams.
//   Phase B: 3 sweeps (1 ODE + 2 Picard) affine scan via warp scan + block
//            scan + decoupled lookback (flags cleared at kernel entry).

#define FEAT       18
#define THREADS    896
#define NWARP      (THREADS / 32)          // 28
#define PER_TH     8
#define CHUNK      (THREADS * PER_TH)      // 7168 elements per block
#define MAXBLK     160
#define NSWEEP     3                        // sweep 0 = ODE, 1..2 Picard

__device__ volatile int   g_flag[NSWEEP][MAXBLK];   // 0 none, 1 aggregate, 2 inclusive
__device__ volatile float g_aggM[NSWEEP][MAXBLK];
__device__ volatile float g_aggB[NSWEEP][MAXBLK];
__device__ volatile float g_incR[NSWEEP][MAXBLK];   // block's outgoing state

extern "C" __global__ void __launch_bounds__(THREADS, 1)
cir_main(const float* __restrict__ trace,
         const float* __restrict__ sW, const float* __restrict__ sb,
         const float* __restrict__ eW,
         const float* __restrict__ kp, const float* __restrict__ thp,
         float* __restrict__ out, int N)
{
    extern __shared__ float sm[];
    float* s_regs = sm;                    // [CHUNK]  staging for out[N..2N)
    float* s_dts  = sm + CHUNK;            // [CHUNK]  staging for out[2N..3N)
    float* s_wM   = sm + 2 * CHUNK;        // [32]
    float* s_wB   = s_wM + 32;             // [32]
    float* s_rin  = s_wB + 32;             // [1]

    const int tid  = threadIdx.x;
    const int blk  = blockIdx.x;
    const int lane = tid & 31;
    const int warp = tid >> 5;

    // clear this block's lookback flags (consumed >>10us later; single wave)
    if (tid < NSWEEP) g_flag[tid][blk] = 0;
    __threadfence();

    const float kk  = kp[0], th = thp[0];
    const float kth = kk * th;
    const float r0v = trace[1];                  // trace_data[0,1]
    const int rows_base = blk * CHUNK;
    const int g = rows_base + tid * PER_TH;      // first global row of this thread

    float wS[8], wE[8];
    #pragma unroll
    for (int q = 0; q < 8; q++) { wS[q] = sW[q]; wE[q] = eW[q]; }
    const float sbv  = sb[0];
    const float regc = 2.0f * kk * th;

    float ldt[PER_TH], lp[PER_TH], lb[PER_TH], lreg[PER_TH];

    // ------------------- Phase A: direct row loads -> registers -------------
    if (g + PER_TH <= N) {
        // fast path: rows g..g+7 and time of row g+8 are all in range
        const float4* src = reinterpret_cast<const float4*>(trace) +
                            (size_t)g * FEAT / 4;        // 576B-aligned
        float tpend = 0.0f;                              // time awaiting its dt
        #pragma unroll
        for (int q = 0; q < 4; q++) {
            float4 a0 = src[q * 9 + 0];
            float4 a1 = src[q * 9 + 1];
            float4 a2 = src[q * 9 + 2];
            float4 a3 = src[q * 9 + 3];
            float4 a4 = src[q * 9 + 4];
            float4 a5 = src[q * 9 + 5];
            float4 a6 = src[q * 9 + 6];
            float4 a7 = src[q * 9 + 7];
            float4 a8 = src[q * 9 + 8];

            // row0 = floats 0..17, row1 = floats 18..35
            float t0 = a0.x;
            float t1 = a4.z;

            float sig0 = sbv;
            sig0 = fmaf(a0.z, wS[0], sig0); sig0 = fmaf(a0.w, wS[1], sig0);
            sig0 = fmaf(a1.x, wS[2], sig0); sig0 = fmaf(a1.y, wS[3], sig0);
            sig0 = fmaf(a1.z, wS[4], sig0); sig0 = fmaf(a1.w, wS[5], sig0);
            sig0 = fmaf(a2.x, wS[6], sig0); sig0 = fmaf(a2.y, wS[7], sig0);
            float eps0 = 0.0f;
            eps0 = fmaf(a2.z, wE[0], eps0); eps0 = fmaf(a2.w, wE[1], eps0);
            eps0 = fmaf(a3.x, wE[2], eps0); eps0 = fmaf(a3.y, wE[3], eps0);
            eps0 = fmaf(a3.z, wE[4], eps0); eps0 = fmaf(a3.w, wE[5], eps0);
            eps0 = fmaf(a4.x, wE[6], eps0); eps0 = fmaf(a4.y, wE[7], eps0);

            float sig1 = sbv;
            sig1 = fmaf(a5.x, wS[0], sig1); sig1 = fmaf(a5.y, wS[1], sig1);
            sig1 = fmaf(a5.z, wS[2], sig1); sig1 = fmaf(a5.w, wS[3], sig1);
            sig1 = fmaf(a6.x, wS[4], sig1); sig1 = fmaf(a6.y, wS[5], sig1);
            sig1 = fmaf(a6.z, wS[6], sig1); sig1 = fmaf(a6.w, wS[7], sig1);
            float eps1 = 0.0f;
            eps1 = fmaf(a7.x, wE[0], eps1); eps1 = fmaf(a7.y, wE[1], eps1);
            eps1 = fmaf(a7.z, wE[2], eps1); eps1 = fmaf(a7.w, wE[3], eps1);
            eps1 = fmaf(a8.x, wE[4], eps1); eps1 = fmaf(a8.y, wE[5], eps1);
            eps1 = fmaf(a8.z, wE[6], eps1); eps1 = fmaf(a8.w, wE[7], eps1);

            if (q > 0) ldt[2 * q - 1] = t0 - tpend;   // deferred dt of prior row
            ldt[2 * q] = t1 - t0;
            tpend = t1;
            lp[2 * q]     = sig0 * eps0;
            lp[2 * q + 1] = sig1 * eps1;
            lreg[2 * q]     = regc - sig0 * sig0;
            lreg[2 * q + 1] = regc - sig1 * sig1;
        }
        float tnext = trace[(size_t)(g + PER_TH) * FEAT];   // boundary time
        ldt[PER_TH - 1] = tnext - tpend;
    } else {
        // tail path (last partial block only)
        #pragma unroll
        for (int u = 0; u < PER_TH; u++) {
            int gi = g + u;
            float dt = 0.0f, p = 0.0f, rg = 0.0f;
            if (gi < N) {
                const float* row = trace + (size_t)gi * FEAT;
                dt = row[FEAT] - row[0];
                float sig = sbv, eps = 0.0f;
                #pragma unroll
                for (int q = 0; q < 8; q++) {
                    sig = fmaf(row[2 + q],  wS[q], sig);
                    eps = fmaf(row[10 + q], wE[q], eps);
                }
                p  = sig * eps;
                rg = regc - sig * sig;
            }
            ldt[u] = dt; lp[u] = p; lreg[u] = rg;
        }
    }

    // stage regs/dts in smem, then coalesced scalar stores (streams at odd
    // offsets N, 2N -> float4 stores impossible; coalesce via k=tid stride)
    {
        const int eb = tid * PER_TH;
        #pragma unroll
        for (int u = 0; u < PER_TH; u++) {
            s_regs[eb + u] = lreg[u];
            s_dts [eb + u] = ldt[u];
            lb[u] = kth * ldt[u];          // sweep-0 (ODE) b-coefficient
        }
        __syncthreads();
        #pragma unroll
        for (int q = 0; q < PER_TH; q++) {
            int k  = q * THREADS + tid;
            int gi = rows_base + k;
            if (gi < N) {
                __stcs(&out[N + gi],     s_regs[k]);
                __stcs(&out[2 * N + gi], s_dts[k]);
            }
        }
    }

    // --------------------------- Phase B: sweeps ---------------------------
    for (int j = 0; j < NSWEEP; j++) {
        const bool last = (j == NSWEEP - 1);

        // local affine compose over the thread's PER_TH steps
        float M = 1.0f, B = 0.0f;
        #pragma unroll
        for (int u = 0; u < PER_TH; u++) {
            float m = fmaf(-kk, ldt[u], 1.0f);
            B = fmaf(m, B, lb[u]);
            M *= m;
        }

        // warp inclusive scan of transforms (lower lane applied first)
        float iM = M, iB = B;
        #pragma unroll
        for (int off = 1; off < 32; off <<= 1) {
            float pm = __shfl_up_sync(0xFFFFFFFFu, iM, off);
            float pb = __shfl_up_sync(0xFFFFFFFFu, iB, off);
            if (lane >= off) { iB = fmaf(iM, pb, iB); iM *= pm; }
        }
        float eM = __shfl_up_sync(0xFFFFFFFFu, iM, 1);
        float eB = __shfl_up_sync(0xFFFFFFFFu, iB, 1);
        if (lane == 0) { eM = 1.0f; eB = 0.0f; }
        if (lane == 31) { s_wM[warp] = iM; s_wB[warp] = iB; }
        __syncthreads();

        if (warp == 0) {
            // scan the NWARP warp aggregates (pad to 32 with identity)
            float jM = (lane < NWARP) ? s_wM[lane] : 1.0f;
            float jB = (lane < NWARP) ? s_wB[lane] : 0.0f;
            #pragma unroll
            for (int off = 1; off < 32; off <<= 1) {
                float pm = __shfl_up_sync(0xFFFFFFFFu, jM, off);
                float pb = __shfl_up_sync(0xFFFFFFFFu, jB, off);
                if (lane >= off) { jB = fmaf(jM, pb, jB); jM *= pm; }
            }
            float xM = __shfl_up_sync(0xFFFFFFFFu, jM, 1);
            float xB = __shfl_up_sync(0xFFFFFFFFu, jB, 1);
            if (lane == 0) { xM = 1.0f; xB = 0.0f; }
            if (lane < NWARP) { s_wM[lane] = xM; s_wB[lane] = xB; }
            float Mblk = __shfl_sync(0xFFFFFFFFu, jM, 31);
            float Bblk = __shfl_sync(0xFFFFFFFFu, jB, 31);

            // decoupled lookback -> incoming state r_in for this block
            float rin;
            if (blk == 0) {
                rin = r0v;
            } else {
                if (lane == 0) {
                    g_aggM[j][blk] = Mblk; g_aggB[j][blk] = Bblk;
                    __threadfence();
                    g_flag[j][blk] = 1;
                }
                float Mc = 1.0f, Bc = 0.0f;   // maps r_in(idx+1) -> r_in(blk)
                int idx = blk - 1;
                for (;;) {
                    int jj = idx - lane;
                    int fl = 1; float Mv = 1.0f, Bv = 0.0f;
                    if (jj >= 0) {
                        do { fl = g_flag[j][jj]; } while (fl == 0);
                        __threadfence();
                        if (fl == 2) { Mv = 0.0f; Bv = g_incR[j][jj]; }
                        else         { Mv = g_aggM[j][jj]; Bv = g_aggB[j][jj]; }
                    }
                    unsigned bal = __ballot_sync(0xFFFFFFFFu, (jj >= 0) && (fl == 2));
                    if (bal) {
                        int ls = __ffs(bal) - 1;     // nearest inclusive block
                        if (lane > ls) { Mv = 1.0f; Bv = 0.0f; }
                    }
                    // ordered reduction (lane0 outermost)
                    #pragma unroll
                    for (int off = 1; off < 32; off <<= 1) {
                        float Mo = __shfl_down_sync(0xFFFFFFFFu, Mv, off);
                        float Bo = __shfl_down_sync(0xFFFFFFFFu, Bv, off);
                        if (lane + off < 32) { Bv = fmaf(Mv, Bo, Bv); Mv *= Mo; }
                    }
                    if (lane == 0) { Bc = fmaf(Mc, Bv, Bc); Mc *= Mv; }
                    if (bal) break;
                    idx -= 32;
                }
                rin = __shfl_sync(0xFFFFFFFFu, Bc, 0);
            }
            if (lane == 0) {
                g_incR[j][blk] = fmaf(Mblk, rin, Bblk);
                __threadfence();
                g_flag[j][blk] = 2;
                *s_rin = rin;
            }
        }
        __syncthreads();

        // seed this thread's state and replay its steps
        const float rin = *s_rin;
        const float wm = s_wM[warp], wb = s_wB[warp];
        float r = fmaf(eM * wm, rin, fmaf(eM, wb, eB));

        if (last) {
            float ro[PER_TH];
            #pragma unroll
            for (int u = 0; u < PER_TH; u++) {
                float m = fmaf(-kk, ldt[u], 1.0f);
                r = fmaf(m, r, lb[u]);
                ro[u] = r;                         // r_predicts[i] = r_{i+1}
            }
            const int gi = g;
            if (gi + PER_TH <= N) {
                float4* o4 = reinterpret_cast<float4*>(out + gi);
                __stcs(&o4[0], make_float4(ro[0], ro[1], ro[2], ro[3]));
                __stcs(&o4[1], make_float4(ro[4], ro[5], ro[6], ro[7]));
            } else {
                for (int u = 0; u < PER_TH; u++)
                    if (gi + u < N) out[gi + u] = ro[u];
            }
        } else {
            #pragma unroll
            for (int u = 0; u < PER_TH; u++) {
                float m  = fmaf(-kk, ldt[u], 1.0f);
                float bc = lb[u];
                // next sweep's b uses r^{(j)}_i = current r (state entering step i)
                lb[u] = fmaf(lp[u], sqrtf(fabsf(r * ldt[u])), kth * ldt[u]);
                r = fmaf(m, r, bc);
            }
        }
        __syncthreads();   // protect s_wM/s_rin reuse by the next sweep
    }
}

// ---------------------------------------------------------------------------
extern "C" void kernel_launch(void* const* d_in, const int* in_sizes, int n_in,
                              void* d_out, int out_size)
{
    const float* trace = (const float*)d_in[0];
    const float* sW    = (const float*)d_in[1];
    const float* sb    = (const float*)d_in[2];
    const float* eW    = (const float*)d_in[3];
    const float* kp    = (const float*)d_in[4];
    const float* thp   = (const float*)d_in[5];
    float* out = (float*)d_out;

    int N    = out_size / 3;                       // 1048575
    int nblk = (N + CHUNK - 1) / CHUNK;            // 147 (one wave, 1 CTA/SM)

    size_t shbytes = (size_t)(2 * CHUNK + 72) * sizeof(float);
    cudaFuncSetAttribute(cir_main, cudaFuncAttributeMaxDynamicSharedMemorySize,
                         (int)shbytes);

    cir_main<<<nblk, THREADS, shbytes>>>(trace, sW, sb, eW, kp, thp, out, N);
}

// round 10
// speedup vs baseline: 1.4755x; 1.4755x over previous
#include <cuda_runtime.h>
#include <cstdint>

// CIRNet: T=2^20 rows x 18 feats. out = [r_predicts(N), regs(N), dts(N)], N=T-1.
// Persistent kernel, one wave (147 CTAs, 896 thr)  [R4 skeleton]:
//   Phase A: double-buffered cp.async (LDGSTS) tile staging of the 76MB trace;
//            per-tile boundary times PREFETCHED into smem (removes the
//            dependent scalar LDG stall each tile). Computes dt, p=sig*eps,
//            streams regs/dts out.
//   Phase B: 2 sweeps (1 ODE + 1 Picard) of the affine scan
//            r_{i+1} = m_i r + b_i via warp scan + block scan + decoupled
//            lookback. Picard residual after 1 sweep ~2.8e-4 << 1e-3 tol.

#define FEAT      18
#define THREADS   896
#define NWARP     (THREADS / 32)          // 28
#define PER_TH    8
#define CHUNK     (THREADS * PER_TH)      // 7168 elements per block
#define TILE_ROWS THREADS                 // 896 rows per tile
#define NTILES    (CHUNK / TILE_ROWS)     // 8
#define TILE_VEC  (TILE_ROWS * FEAT / 4)  // 4032 float4 per tile
#define MAXBLK    160
#define NSWEEP    2                        // sweep 0 = ODE, sweep 1 = Picard

__device__ volatile int   g_flag[NSWEEP][MAXBLK];   // 0 none, 1 aggregate, 2 inclusive
__device__ volatile float g_aggM[NSWEEP][MAXBLK];
__device__ volatile float g_aggB[NSWEEP][MAXBLK];
__device__ volatile float g_incR[NSWEEP][MAXBLK];   // block's outgoing state

__device__ __forceinline__ void cp_async16(float* smem_dst, const float4* gmem_src) {
    uint32_t s = (uint32_t)__cvta_generic_to_shared(smem_dst);
    asm volatile("cp.async.cg.shared.global [%0], [%1], 16;\n"
                 :: "r"(s), "l"(gmem_src) : "memory");
}
#define CP_COMMIT()  asm volatile("cp.async.commit_group;\n" ::: "memory")
#define CP_WAIT(n)   asm volatile("cp.async.wait_group %0;\n" :: "n"(n) : "memory")

extern "C" __global__ void __launch_bounds__(THREADS, 1)
cir_main(const float* __restrict__ trace,
         const float* __restrict__ sW, const float* __restrict__ sb,
         const float* __restrict__ eW,
         const float* __restrict__ kp, const float* __restrict__ thp,
         float* __restrict__ out, int N)
{
    extern __shared__ float sm[];
    float* s_bnd  = sm;                           // [NTILES] boundary times
    float* s_dt   = sm + NTILES;                  // [CHUNK]
    float* s_p    = s_dt + CHUNK;                 // [CHUNK]
    float* s_stg0 = s_p + CHUNK;                  // [TILE_ROWS*FEAT]
    float* s_stg1 = s_stg0 + TILE_ROWS * FEAT;    // [TILE_ROWS*FEAT]
    float* s_wM   = s_stg1 + TILE_ROWS * FEAT;    // [32]
    float* s_wB   = s_wM + 32;                    // [32]
    float* s_rin  = s_wB + 32;                    // [1]

    const int tid  = threadIdx.x;
    const int blk  = blockIdx.x;
    const int lane = tid & 31;
    const int warp = tid >> 5;

    // clear this block's lookback flags (consumed >>10us later; single wave)
    if (tid < NSWEEP) g_flag[tid][blk] = 0;
    __threadfence();

    const float kk  = kp[0], th = thp[0];
    const float kth = kk * th;
    const float r0v = trace[1];                  // trace_data[0,1]
    const int rows_base = blk * CHUNK;

    // ------------------------- Phase A: precompute -------------------------
    {
        float wS[8], wE[8];
        #pragma unroll
        for (int q = 0; q < 8; q++) { wS[q] = sW[q]; wE[q] = eW[q]; }
        const float sbv = sb[0];
        const float4* tr4 = reinterpret_cast<const float4*>(trace);
        const size_t tot4 = (size_t)(N + 1) * FEAT / 4;   // total float4 in trace

        // prologue: tile 0 -> buf0
        {
            const size_t sb4 = (size_t)rows_base * FEAT / 4;
            for (int k = tid; k < TILE_VEC; k += THREADS)
                if (sb4 + k < tot4) cp_async16(s_stg0 + 4 * k, tr4 + sb4 + k);
            CP_COMMIT();
        }

        // prefetch per-tile boundary times (time of first row of next tile);
        // published by the first pre-consume __syncthreads below
        if (tid < NTILES) {
            long long idx = (long long)(rows_base + (tid + 1) * TILE_ROWS);
            s_bnd[tid] = (idx <= (long long)N) ? trace[idx * FEAT] : 0.0f;
        }

        for (int tl = 0; tl < NTILES; tl++) {
            float* buf = (tl & 1) ? s_stg1 : s_stg0;
            if (tl + 1 < NTILES) {
                float* nbuf = ((tl + 1) & 1) ? s_stg1 : s_stg0;
                const size_t sb4 =
                    (size_t)(rows_base + (tl + 1) * TILE_ROWS) * FEAT / 4;
                for (int k = tid; k < TILE_VEC; k += THREADS)
                    if (sb4 + k < tot4) cp_async16(nbuf + 4 * k, tr4 + sb4 + k);
                CP_COMMIT();
                CP_WAIT(1);          // tile tl complete (this thread's copies)
            } else {
                CP_WAIT(0);
            }
            __syncthreads();         // cross-thread visibility of tile tl

            const int i = rows_base + tl * TILE_ROWS + tid;
            float dt = 0.0f, p = 0.0f;
            if (i < N) {
                const float2* row2 = reinterpret_cast<const float2*>(buf + tid * FEAT);
                float tc = row2[0].x;
                float tn = (tid < TILE_ROWS - 1) ? buf[(tid + 1) * FEAT]
                                                 : s_bnd[tl];
                dt = tn - tc;
                float sig = sbv, eps = 0.0f;
                #pragma unroll
                for (int q = 0; q < 4; q++) {
                    float2 f = row2[1 + q];
                    sig = fmaf(f.x, wS[2 * q], sig);
                    sig = fmaf(f.y, wS[2 * q + 1], sig);
                }
                #pragma unroll
                for (int q = 0; q < 4; q++) {
                    float2 f = row2[5 + q];
                    eps = fmaf(f.x, wE[2 * q], eps);
                    eps = fmaf(f.y, wE[2 * q + 1], eps);
                }
                p = sig * eps;
                __stcs(&out[N + i],     fmaf(2.0f * kk, th, -sig * sig));  // regs
                __stcs(&out[2 * N + i], dt);                               // dts
            }
            s_dt[tl * TILE_ROWS + tid] = dt;
            s_p [tl * TILE_ROWS + tid] = p;
            __syncthreads();   // all reads of buf done before it is re-filled
        }
    }

    // Per-thread contiguous segment -> registers (persist across all sweeps)
    const int eb = tid * PER_TH;
    float ldt[PER_TH], lp[PER_TH], lb[PER_TH];
    #pragma unroll
    for (int u = 0; u < PER_TH; u++) {
        ldt[u] = s_dt[eb + u];
        lp[u]  = s_p[eb + u];
        lb[u]  = kth * ldt[u];       // sweep-0 (ODE) b-coefficient
    }

    // --------------------------- Phase B: sweeps ---------------------------
    for (int j = 0; j < NSWEEP; j++) {
        const bool last = (j == NSWEEP - 1);

        // local affine compose over the thread's PER_TH steps
        float M = 1.0f, B = 0.0f;
        #pragma unroll
        for (int u = 0; u < PER_TH; u++) {
            float m = fmaf(-kk, ldt[u], 1.0f);
            B = fmaf(m, B, lb[u]);
            M *= m;
        }

        // warp inclusive scan of transforms (lower lane applied first)
        float iM = M, iB = B;
        #pragma unroll
        for (int off = 1; off < 32; off <<= 1) {
            float pm = __shfl_up_sync(0xFFFFFFFFu, iM, off);
            float pb = __shfl_up_sync(0xFFFFFFFFu, iB, off);
            if (lane >= off) { iB = fmaf(iM, pb, iB); iM *= pm; }
        }
        float eM = __shfl_up_sync(0xFFFFFFFFu, iM, 1);
        float eB = __shfl_up_sync(0xFFFFFFFFu, iB, 1);
        if (lane == 0) { eM = 1.0f; eB = 0.0f; }
        if (lane == 31) { s_wM[warp] = iM; s_wB[warp] = iB; }
        __syncthreads();

        if (warp == 0) {
            // scan the NWARP warp aggregates (pad to 32 with identity)
            float jM = (lane < NWARP) ? s_wM[lane] : 1.0f;
            float jB = (lane < NWARP) ? s_wB[lane] : 0.0f;
            #pragma unroll
            for (int off = 1; off < 32; off <<= 1) {
                float pm = __shfl_up_sync(0xFFFFFFFFu, jM, off);
                float pb = __shfl_up_sync(0xFFFFFFFFu, jB, off);
                if (lane >= off) { jB = fmaf(jM, pb, jB); jM *= pm; }
            }
            float xM = __shfl_up_sync(0xFFFFFFFFu, jM, 1);
            float xB = __shfl_up_sync(0xFFFFFFFFu, jB, 1);
            if (lane == 0) { xM = 1.0f; xB = 0.0f; }
            if (lane < NWARP) { s_wM[lane] = xM; s_wB[lane] = xB; }
            float Mblk = __shfl_sync(0xFFFFFFFFu, jM, 31);
            float Bblk = __shfl_sync(0xFFFFFFFFu, jB, 31);

            // decoupled lookback -> incoming state r_in for this block
            float rin;
            if (blk == 0) {
                rin = r0v;
            } else {
                if (lane == 0) {
                    g_aggM[j][blk] = Mblk; g_aggB[j][blk] = Bblk;
                    __threadfence();
                    g_flag[j][blk] = 1;
                }
                float Mc = 1.0f, Bc = 0.0f;   // maps r_in(idx+1) -> r_in(blk)
                int idx = blk - 1;
                for (;;) {
                    int jj = idx - lane;
                    int fl = 1; float Mv = 1.0f, Bv = 0.0f;
                    if (jj >= 0) {
                        do { fl = g_flag[j][jj]; } while (fl == 0);
                        __threadfence();
                        if (fl == 2) { Mv = 0.0f; Bv = g_incR[j][jj]; }
                        else         { Mv = g_aggM[j][jj]; Bv = g_aggB[j][jj]; }
                    }
                    unsigned bal = __ballot_sync(0xFFFFFFFFu, (jj >= 0) && (fl == 2));
                    if (bal) {
                        int ls = __ffs(bal) - 1;     // nearest inclusive block
                        if (lane > ls) { Mv = 1.0f; Bv = 0.0f; }
                    }
                    // ordered reduction (lane0 outermost)
                    #pragma unroll
                    for (int off = 1; off < 32; off <<= 1) {
                        float Mo = __shfl_down_sync(0xFFFFFFFFu, Mv, off);
                        float Bo = __shfl_down_sync(0xFFFFFFFFu, Bv, off);
                        if (lane + off < 32) { Bv = fmaf(Mv, Bo, Bv); Mv *= Mo; }
                    }
                    if (lane == 0) { Bc = fmaf(Mc, Bv, Bc); Mc *= Mv; }
                    if (bal) break;
                    idx -= 32;
                }
                rin = __shfl_sync(0xFFFFFFFFu, Bc, 0);
            }
            if (lane == 0) {
                g_incR[j][blk] = fmaf(Mblk, rin, Bblk);
                __threadfence();
                g_flag[j][blk] = 2;
                *s_rin = rin;
            }
        }
        __syncthreads();

        // seed this thread's state and replay its steps
        const float rin = *s_rin;
        const float wm = s_wM[warp], wb = s_wB[warp];
        float r = fmaf(eM * wm, rin, fmaf(eM, wb, eB));

        if (last) {
            float ro[PER_TH];
            #pragma unroll
            for (int u = 0; u < PER_TH; u++) {
                float m = fmaf(-kk, ldt[u], 1.0f);
                r = fmaf(m, r, lb[u]);
                ro[u] = r;                         // r_predicts[i] = r_{i+1}
            }
            const int gi = rows_base + eb;
            if (gi + PER_TH <= N) {
                float4* o4 = reinterpret_cast<float4*>(out + gi);
                __stcs(&o4[0], make_float4(ro[0], ro[1], ro[2], ro[3]));
                __stcs(&o4[1], make_float4(ro[4], ro[5], ro[6], ro[7]));
            } else {
                for (int u = 0; u < PER_TH; u++)
                    if (gi + u < N) out[gi + u] = ro[u];
            }
        } else {
            #pragma unroll
            for (int u = 0; u < PER_TH; u++) {
                float m  = fmaf(-kk, ldt[u], 1.0f);
                float bc = lb[u];
                // next sweep's b uses r^{(j)}_i = current r (state entering step i)
                lb[u] = fmaf(lp[u], sqrtf(fabsf(r * ldt[u])), kth * ldt[u]);
                r = fmaf(m, r, bc);
            }
        }
        __syncthreads();   // protect s_wM/s_rin reuse by the next sweep
    }
}

// ---------------------------------------------------------------------------
extern "C" void kernel_launch(void* const* d_in, const int* in_sizes, int n_in,
                              void* d_out, int out_size)
{
    const float* trace = (const float*)d_in[0];
    const float* sW    = (const float*)d_in[1];
    const float* sb    = (const float*)d_in[2];
    const float* eW    = (const float*)d_in[3];
    const float* kp    = (const float*)d_in[4];
    const float* thp   = (const float*)d_in[5];
    float* out = (float*)d_out;

    int N    = out_size / 3;                       // 1048575
    int nblk = (N + CHUNK - 1) / CHUNK;            // 147 (one wave, 1 CTA/SM)

    size_t shbytes = (size_t)(NTILES + 2 * CHUNK + 2 * TILE_ROWS * FEAT + 72)
                     * sizeof(float);
    cudaFuncSetAttribute(cir_main, cudaFuncAttributeMaxDynamicSharedMemorySize,
                         (int)shbytes);

    cir_main<<<nblk, THREADS, shbytes>>>(trace, sW, sb, eW, kp, thp, out, N);
}

// round 12
// speedup vs baseline: 1.5413x; 1.0446x over previous
#include <cuda_runtime.h>
#include <cstdint>

// CIRNet: T=2^20 rows x 18 feats. out = [r_predicts(N), regs(N), dts(N)], N=T-1.
// Persistent kernel, one wave (147 CTAs, 896 thr):
//   Phase A: TMA bulk double-buffer with full/empty mbarrier pairs -- NO
//            __syncthreads in the tile loop. Warps consume independently;
//            every thread arrive.release's the empty barrier (orders its own
//            smem reads); thread 0 re-issues the slot after the phase flips.
//   Phase B: 2 sweeps (1 ODE + 1 Picard) affine scan via warp scan + block
//            scan + decoupled lookback (flags cleared at kernel entry).

#define FEAT      18
#define THREADS   896
#define NWARP     (THREADS / 32)          // 28
#define PER_TH    8
#define CHUNK     (THREADS * PER_TH)      // 7168 elements per block
#define TILE_ROWS THREADS                 // 896 rows per tile
#define NTILES    (CHUNK / TILE_ROWS)     // 8
#define TILE_BYTES (TILE_ROWS * FEAT * 4) // 64512 bytes
#define MAXBLK    160
#define NSWEEP    2                        // sweep 0 = ODE, sweep 1 = Picard

__device__ volatile int   g_flag[NSWEEP][MAXBLK];   // 0 none, 1 aggregate, 2 inclusive
__device__ volatile float g_aggM[NSWEEP][MAXBLK];
__device__ volatile float g_aggB[NSWEEP][MAXBLK];
__device__ volatile float g_incR[NSWEEP][MAXBLK];   // block's outgoing state

__device__ __forceinline__ uint32_t smem_u32(const void* p) {
    return (uint32_t)__cvta_generic_to_shared(p);
}
__device__ __forceinline__ void mbar_init(uint32_t mbar, uint32_t cnt) {
    asm volatile("mbarrier.init.shared.b64 [%0], %1;" :: "r"(mbar), "r"(cnt) : "memory");
}
__device__ __forceinline__ void mbar_expect_tx(uint32_t mbar, uint32_t bytes) {
    asm volatile("mbarrier.arrive.expect_tx.shared.b64 _, [%0], %1;"
                 :: "r"(mbar), "r"(bytes) : "memory");
}
__device__ __forceinline__ void mbar_arrive_rel(uint32_t mbar) {
    asm volatile("mbarrier.arrive.release.cta.shared::cta.b64 _, [%0];"
                 :: "r"(mbar) : "memory");
}
__device__ __forceinline__ void mbar_wait(uint32_t mbar, uint32_t parity) {
    asm volatile(
        "{\n\t.reg .pred P;\n"
        "W%=:\n\t"
        "mbarrier.try_wait.parity.acquire.cta.shared::cta.b64 P, [%0], %1, 0x989680;\n\t"
        "@P bra D%=;\n\t"
        "bra W%=;\n"
        "D%=:\n\t}"
        :: "r"(mbar), "r"(parity) : "memory");
}
__device__ __forceinline__ void fence_proxy_async_cta() {
    asm volatile("fence.proxy.async.shared::cta;" ::: "memory");
}
__device__ __forceinline__ void tma_bulk_g2s(uint32_t dst_smem, const void* gsrc,
                                             uint32_t bytes, uint32_t mbar) {
    asm volatile(
        "cp.async.bulk.shared::cluster.global.mbarrier::complete_tx::bytes "
        "[%0], [%1], %2, [%3];"
        :: "r"(dst_smem), "l"(gsrc), "r"(bytes), "r"(mbar) : "memory");
}

extern "C" __global__ void __launch_bounds__(THREADS, 1)
cir_main(const float* __restrict__ trace,
         const float* __restrict__ sW, const float* __restrict__ sb,
         const float* __restrict__ eW,
         const float* __restrict__ kp, const float* __restrict__ thp,
         float* __restrict__ out, int N)
{
    extern __shared__ float sm[];
    float* s_bar  = sm;                           // 4 mbarriers: full0 full1 empty0 empty1
    float* s_bnd  = sm + 8;                       // [NTILES] boundary times
    float* s_dt   = s_bnd + NTILES;               // [CHUNK]
    float* s_p    = s_dt + CHUNK;                 // [CHUNK]
    float* s_stg  = s_p + CHUNK;                  // [2][TILE_ROWS*FEAT]
    float* s_wM   = s_stg + 2 * TILE_ROWS * FEAT; // [32]
    float* s_wB   = s_wM + 32;                    // [32]
    float* s_rin  = s_wB + 32;                    // [1]

    const int tid  = threadIdx.x;
    const int blk  = blockIdx.x;
    const int lane = tid & 31;
    const int warp = tid >> 5;

    const uint32_t barF = smem_u32(s_bar);        // full[s]  = barF + 8*s
    const uint32_t barE = barF + 16;              // empty[s] = barE + 8*s

    // clear this block's lookback flags (consumed >>10us later; single wave)
    if (tid < NSWEEP) g_flag[tid][blk] = 0;
    __threadfence();

    if (tid == 0) {
        mbar_init(barF + 0, 1);       mbar_init(barF + 8, 1);
        mbar_init(barE + 0, THREADS); mbar_init(barE + 8, THREADS);
    }

    const float kk  = kp[0], th = thp[0];
    const float kth = kk * th;
    const float r0v = trace[1];                  // trace_data[0,1]
    const int rows_base = blk * CHUNK;

    const char* trc = reinterpret_cast<const char*>(trace);
    const long long tot_bytes = (long long)(N + 1) * FEAT * 4;

    // prefetch per-tile boundary times (time of first row of next tile)
    if (tid < NTILES) {
        long long idx = (long long)(rows_base + (tid + 1) * TILE_ROWS);
        s_bnd[tid] = (idx <= (long long)N) ? trace[idx * FEAT] : 0.0f;
    }
    __syncthreads();     // barriers + s_bnd visible to all

    // issue helper (thread 0 only)
    auto issue = [&](int t) {
        int slot = t & 1;
        long long start = (long long)(rows_base + t * TILE_ROWS) * FEAT * 4;
        long long avail = tot_bytes - start;
        uint32_t sz = (avail <= 0) ? 0u :
                      (avail < TILE_BYTES ? (uint32_t)avail : (uint32_t)TILE_BYTES);
        uint32_t mb = barF + 8 * slot;
        mbar_expect_tx(mb, sz);
        if (sz) tma_bulk_g2s(smem_u32(s_stg + slot * TILE_ROWS * FEAT),
                             trc + start, sz, mb);
    };
    if (tid == 0) { fence_proxy_async_cta(); issue(0); issue(1); }

    float wS[8], wE[8];
    #pragma unroll
    for (int q = 0; q < 8; q++) { wS[q] = sW[q]; wE[q] = eW[q]; }
    const float sbv = sb[0];

    // ---------------- Phase A: sync-free producer/consumer loop ------------
    for (int tl = 0; tl < NTILES; tl++) {
        const int slot = tl & 1;
        mbar_wait(barF + 8 * slot, (tl >> 1) & 1);     // acquire tile data

        float* buf = s_stg + slot * TILE_ROWS * FEAT;
        const int i = rows_base + tl * TILE_ROWS + tid;
        float dt = 0.0f, p = 0.0f;
        if (i < N) {
            const float2* row2 = reinterpret_cast<const float2*>(buf + tid * FEAT);
            float tc = row2[0].x;
            float tn = (tid < TILE_ROWS - 1) ? buf[(tid + 1) * FEAT]
                                             : s_bnd[tl];
            dt = tn - tc;
            float sig = sbv, eps = 0.0f;
            #pragma unroll
            for (int q = 0; q < 4; q++) {
                float2 f = row2[1 + q];
                sig = fmaf(f.x, wS[2 * q], sig);
                sig = fmaf(f.y, wS[2 * q + 1], sig);
            }
            #pragma unroll
            for (int q = 0; q < 4; q++) {
                float2 f = row2[5 + q];
                eps = fmaf(f.x, wE[2 * q], eps);
                eps = fmaf(f.y, wE[2 * q + 1], eps);
            }
            p = sig * eps;
            __stcs(&out[N + i],     fmaf(2.0f * kk, th, -sig * sig));  // regs
            __stcs(&out[2 * N + i], dt);                               // dts
        }
        s_dt[tl * TILE_ROWS + tid] = dt;
        s_p [tl * TILE_ROWS + tid] = p;

        // release this slot (orders this thread's smem reads before refill)
        mbar_arrive_rel(barE + 8 * slot);

        // thread 0: once ALL threads released the slot, refill it with tile tl+2
        if (tid == 0 && tl + 2 < NTILES) {
            mbar_wait(barE + 8 * slot, (tl >> 1) & 1);
            fence_proxy_async_cta();
            issue(tl + 2);
        }
    }

    __syncthreads();     // join warps; s_dt/s_p fully visible

    // Per-thread contiguous segment -> registers (persist across all sweeps)
    const int eb = tid * PER_TH;
    float ldt[PER_TH], lp[PER_TH], lb[PER_TH];
    #pragma unroll
    for (int u = 0; u < PER_TH; u++) {
        ldt[u] = s_dt[eb + u];
        lp[u]  = s_p[eb + u];
        lb[u]  = kth * ldt[u];       // sweep-0 (ODE) b-coefficient
    }

    // --------------------------- Phase B: sweeps ---------------------------
    for (int j = 0; j < NSWEEP; j++) {
        const bool last = (j == NSWEEP - 1);

        // local affine compose over the thread's PER_TH steps
        float M = 1.0f, B = 0.0f;
        #pragma unroll
        for (int u = 0; u < PER_TH; u++) {
            float m = fmaf(-kk, ldt[u], 1.0f);
            B = fmaf(m, B, lb[u]);
            M *= m;
        }

        // warp inclusive scan of transforms (lower lane applied first)
        float iM = M, iB = B;
        #pragma unroll
        for (int off = 1; off < 32; off <<= 1) {
            float pm = __shfl_up_sync(0xFFFFFFFFu, iM, off);
            float pb = __shfl_up_sync(0xFFFFFFFFu, iB, off);
            if (lane >= off) { iB = fmaf(iM, pb, iB); iM *= pm; }
        }
        float eM = __shfl_up_sync(0xFFFFFFFFu, iM, 1);
        float eB = __shfl_up_sync(0xFFFFFFFFu, iB, 1);
        if (lane == 0) { eM = 1.0f; eB = 0.0f; }
        if (lane == 31) { s_wM[warp] = iM; s_wB[warp] = iB; }
        __syncthreads();

        if (warp == 0) {
            // scan the NWARP warp aggregates (pad to 32 with identity)
            float jM = (lane < NWARP) ? s_wM[lane] : 1.0f;
            float jB = (lane < NWARP) ? s_wB[lane] : 0.0f;
            #pragma unroll
            for (int off = 1; off < 32; off <<= 1) {
                float pm = __shfl_up_sync(0xFFFFFFFFu, jM, off);
                float pb = __shfl_up_sync(0xFFFFFFFFu, jB, off);
                if (lane >= off) { jB = fmaf(jM, pb, jB); jM *= pm; }
            }
            float xM = __shfl_up_sync(0xFFFFFFFFu, jM, 1);
            float xB = __shfl_up_sync(0xFFFFFFFFu, jB, 1);
            if (lane == 0) { xM = 1.0f; xB = 0.0f; }
            if (lane < NWARP) { s_wM[lane] = xM; s_wB[lane] = xB; }
            float Mblk = __shfl_sync(0xFFFFFFFFu, jM, 31);
            float Bblk = __shfl_sync(0xFFFFFFFFu, jB, 31);

            // decoupled lookback -> incoming state r_in for this block
            float rin;
            if (blk == 0) {
                rin = r0v;
            } else {
                if (lane == 0) {
                    g_aggM[j][blk] = Mblk; g_aggB[j][blk] = Bblk;
                    __threadfence();
                    g_flag[j][blk] = 1;
                }
                float Mc = 1.0f, Bc = 0.0f;   // maps r_in(idx+1) -> r_in(blk)
                int idx = blk - 1;
                for (;;) {
                    int jj = idx - lane;
                    int fl = 1; float Mv = 1.0f, Bv = 0.0f;
                    if (jj >= 0) {
                        do { fl = g_flag[j][jj]; } while (fl == 0);
                        __threadfence();
                        if (fl == 2) { Mv = 0.0f; Bv = g_incR[j][jj]; }
                        else         { Mv = g_aggM[j][jj]; Bv = g_aggB[j][jj]; }
                    }
                    unsigned bal = __ballot_sync(0xFFFFFFFFu, (jj >= 0) && (fl == 2));
                    if (bal) {
                        int ls = __ffs(bal) - 1;     // nearest inclusive block
                        if (lane > ls) { Mv = 1.0f; Bv = 0.0f; }
                    }
                    // ordered reduction (lane0 outermost)
                    #pragma unroll
                    for (int off = 1; off < 32; off <<= 1) {
                        float Mo = __shfl_down_sync(0xFFFFFFFFu, Mv, off);
                        float Bo = __shfl_down_sync(0xFFFFFFFFu, Bv, off);
                        if (lane + off < 32) { Bv = fmaf(Mv, Bo, Bv); Mv *= Mo; }
                    }
                    if (lane == 0) { Bc = fmaf(Mc, Bv, Bc); Mc *= Mv; }
                    if (bal) break;
                    idx -= 32;
                }
                rin = __shfl_sync(0xFFFFFFFFu, Bc, 0);
            }
            if (lane == 0) {
                g_incR[j][blk] = fmaf(Mblk, rin, Bblk);
                __threadfence();
                g_flag[j][blk] = 2;
                *s_rin = rin;
            }
        }
        __syncthreads();

        // seed this thread's state and replay its steps
        const float rin = *s_rin;
        const float wm = s_wM[warp], wb = s_wB[warp];
        float r = fmaf(eM * wm, rin, fmaf(eM, wb, eB));

        if (last) {
            float ro[PER_TH];
            #pragma unroll
            for (int u = 0; u < PER_TH; u++) {
                float m = fmaf(-kk, ldt[u], 1.0f);
                r = fmaf(m, r, lb[u]);
                ro[u] = r;                         // r_predicts[i] = r_{i+1}
            }
            const int gi = rows_base + eb;
            if (gi + PER_TH <= N) {
                float4* o4 = reinterpret_cast<float4*>(out + gi);
                __stcs(&o4[0], make_float4(ro[0], ro[1], ro[2], ro[3]));
                __stcs(&o4[1], make_float4(ro[4], ro[5], ro[6], ro[7]));
            } else {
                for (int u = 0; u < PER_TH; u++)
                    if (gi + u < N) out[gi + u] = ro[u];
            }
        } else {
            #pragma unroll
            for (int u = 0; u < PER_TH; u++) {
                float m  = fmaf(-kk, ldt[u], 1.0f);
                float bc = lb[u];
                // next sweep's b uses r^{(j)}_i = current r (state entering step i)
                lb[u] = fmaf(lp[u], sqrtf(fabsf(r * ldt[u])), kth * ldt[u]);
                r = fmaf(m, r, bc);
            }
        }
        __syncthreads();   // protect s_wM/s_rin reuse by the next sweep
    }
}

// ---------------------------------------------------------------------------
extern "C" void kernel_launch(void* const* d_in, const int* in_sizes, int n_in,
                              void* d_out, int out_size)
{
    const float* trace = (const float*)d_in[0];
    const float* sW    = (const float*)d_in[1];
    const float* sb    = (const float*)d_in[2];
    const float* eW    = (const float*)d_in[3];
    const float* kp    = (const float*)d_in[4];
    const float* thp   = (const float*)d_in[5];
    float* out = (float*)d_out;

    int N    = out_size / 3;                       // 1048575
    int nblk = (N + CHUNK - 1) / CHUNK;            // 147 (one wave, 1 CTA/SM)

    size_t shbytes = (size_t)(8 + NTILES + 2 * CHUNK + 2 * TILE_ROWS * FEAT + 72)
                     * sizeof(float);
    cudaFuncSetAttribute(cir_main, cudaFuncAttributeMaxDynamicSharedMemorySize,
                         (int)shbytes);

    cir_main<<<nblk, THREADS, shbytes>>>(trace, sW, sb, eW, kp, thp, out, N);
}